// round 13
// baseline (speedup 1.0000x reference)
#include <cuda_runtime.h>
#include <math.h>
#include <stdint.h>

#define NPTS    8192
#define NB      2
#define TNN     128                        // threads per NN block (4 warps)
#define NWARP   (TNN / 32)                 // 4
#define QPW     4                          // queries per warp (lean regs)
#define QPB     (NWARP * QPW)              // 16 queries per block
#define SEG     1024                       // candidate tile
#define NPAIR   (SEG / 2)                  // 512 pairs
#define NSTEP   (SEG / 64)                 // 16 warp-steps
#define GSTEP   8                          // steps per tracking group
#define NGRP    (NSTEP / GSTEP)            // 2 groups
#define NSEG    (NPTS / SEG)               // 8
#define NQC     (NPTS / QPB)               // 512 query chunks
#define NQ_TOTAL (2 * NB * NPTS)           // 32768
#define NN_BLOCKS (2 * NB * NQC * NSEG)    // 16384
#define TLOSS   256
#define LOSS_BLOCKS (NQ_TOTAL / TLOSS)     // 128

// Scratch. g_segkeys[seg][global_q]: per-tile winner, plain stores (every slot
// rewritten each replay -> no init). Key = (order-preserving score bits << 32 |
// candidate idx): u64 min == (min score, lowest idx) == reference tie-break.
__device__ unsigned long long g_segkeys[NSEG * NQ_TOTAL];
__device__ unsigned long long g_keys[NQ_TOTAL];
__device__ int                g_counts[NQ_TOTAL];
__device__ double             g_sum;
__device__ unsigned int       g_done;

// ---- f32x2 packed FMA (sm_103a) -------------------------------------------
__device__ __forceinline__ unsigned long long ffma2(
    unsigned long long a, unsigned long long b, unsigned long long c) {
    unsigned long long d;
    asm("fma.rn.f32x2 %0, %1, %2, %3;" : "=l"(d) : "l"(a), "l"(b), "l"(c));
    return d;
}
__device__ __forceinline__ unsigned long long fdup2(float v) {
    unsigned long long r;
    asm("mov.b64 %0, {%1, %1};" : "=l"(r) : "f"(v));
    return r;
}
__device__ __forceinline__ float2 unpack2(unsigned long long v) {
    float2 r;
    asm("mov.b64 {%0, %1}, %2;" : "=f"(r.x), "=f"(r.y) : "l"(v));
    return r;
}

// ---------------------------------------------------------------------------
// Kernel 1: NN scan — broadcast-free, lean registers, group tracking.
// Queries: 4 per warp in packed uniform regs (24 regs, not 48 -> 28 warps/SM).
// Candidates: lane-strided pair-packed AoS SMEM -> conflict-free LDS.128.
// Inner loop per step/query: 3 FFMA2 + 2 FMNMX. Group select every 8 steps.
// Winning (step,j) recovered bit-identically; cross-lane merge via u64-key
// butterfly (exact lowest-index tie-break).
// ---------------------------------------------------------------------------
__global__ __launch_bounds__(TNN, 7) void dacd_nn_kernel(
    const float* __restrict__ x, const float* __restrict__ gt)
{
    __shared__ __align__(16) float4 sA[NPAIR];  // (c0a,c0b,c1a,c1b) 8KB
    __shared__ __align__(16) float4 sB[NPAIR];  // (c2a,c2b,wa,wb)   8KB

    const int blk = blockIdx.x;
    const int seg = blk & (NSEG - 1);          // bits [0,3)
    const int qc  = (blk >> 3) & (NQC - 1);    // bits [3,12)
    const int b   = (blk >> 12) & 1;
    const int dir = (blk >> 13) & 1;

    // Zero counts / sum / ticket (replaces init kernel).
    if (threadIdx.x < NQ_TOTAL / NN_BLOCKS)    // 2
        g_counts[blk * (NQ_TOTAL / NN_BLOCKS) + threadIdx.x] = 0;
    if (blk == 0 && threadIdx.x == 0) { g_sum = 0.0; g_done = 0u; }

    const float* qry = dir ? gt : x;
    const float* cnd = dir ? x : gt;

    const float* c0p = cnd + (b * 3 + 0) * NPTS + seg * SEG;
    const float* c1p = cnd + (b * 3 + 1) * NPTS + seg * SEG;
    const float* c2p = cnd + (b * 3 + 2) * NPTS + seg * SEG;

    // Tile load: pair-packed AoS (4 iterations).
    for (int p = threadIdx.x; p < NPAIR; p += TNN) {
        float2 c0 = *(const float2*)(c0p + 2 * p);
        float2 c1 = *(const float2*)(c1p + 2 * p);
        float2 c2 = *(const float2*)(c2p + 2 * p);
        float wa = fmaf(c0.x, c0.x, fmaf(c1.x, c1.x, c2.x * c2.x));
        float wb = fmaf(c0.y, c0.y, fmaf(c1.y, c1.y, c2.y * c2.y));
        sA[p] = make_float4(c0.x, c0.y, c1.x, c1.y);
        sB[p] = make_float4(c2.x, c2.y, wa, wb);
    }
    __syncthreads();

    const int lane = threadIdx.x & 31;
    const int wid  = threadIdx.x >> 5;
    const int qbase = qc * QPB + wid * QPW;

    const float* qb = qry + b * 3 * NPTS;
    unsigned long long n0[QPW], n1[QPW], n2[QPW];
#pragma unroll
    for (int k = 0; k < QPW; k++) {
        int q = qbase + k;
        n0[k] = fdup2(-2.0f * qb[0 * NPTS + q]);
        n1[k] = fdup2(-2.0f * qb[1 * NPTS + q]);
        n2[k] = fdup2(-2.0f * qb[2 * NPTS + q]);
    }

    const float INF = __int_as_float(0x7f800000);
    float best[QPW];
    int   bg[QPW];
#pragma unroll
    for (int k = 0; k < QPW; k++) { best[k] = INF; bg[k] = 0; }

#pragma unroll 1
    for (int g = 0; g < NGRP; g++) {               // 2 groups
        float gm[QPW];
#pragma unroll
        for (int k = 0; k < QPW; k++) gm[k] = INF;

#pragma unroll
        for (int s = 0; s < GSTEP; s++) {          // 8 steps
            const int idx = (g * GSTEP + s) * 32 + lane;
            ulonglong2 va = *(const ulonglong2*)&sA[idx];
            ulonglong2 vb = *(const ulonglong2*)&sB[idx];
#pragma unroll
            for (int k = 0; k < QPW; k++) {
                unsigned long long t = ffma2(n2[k], vb.x, vb.y);
                t = ffma2(n1[k], va.y, t);
                t = ffma2(n0[k], va.x, t);
                float2 s2 = unpack2(t);
                gm[k] = fminf(gm[k], fminf(s2.x, s2.y));
            }
        }
#pragma unroll
        for (int k = 0; k < QPW; k++) {
            bool sel = gm[k] < best[k];    // strict: earlier group wins ties
            bg[k]   = sel ? g : bg[k];
            best[k] = fminf(best[k], gm[k]);
        }
    }

    // Epilogue: rescan winning group bit-identically; first (lowest-idx) hit
    // per lane; exact global merge via u64-key butterfly.
    unsigned long long* segbase =
        g_segkeys + seg * NQ_TOTAL + (dir * NB + b) * NPTS;
#pragma unroll 1
    for (int k = 0; k < QPW; k++) {
        int hit = -1;                               // s*2 + j, first hit
#pragma unroll 1
        for (int s = 0; s < GSTEP; s++) {
            const int idx = (bg[k] * GSTEP + s) * 32 + lane;
            ulonglong2 va = *(const ulonglong2*)&sA[idx];
            ulonglong2 vb = *(const ulonglong2*)&sB[idx];
            unsigned long long t = ffma2(n2[k], vb.x, vb.y);
            t = ffma2(n1[k], va.y, t);
            t = ffma2(n0[k], va.x, t);
            float2 s2 = unpack2(t);
            if (hit < 0) {
                if      (s2.x <= best[k]) hit = s * 2 + 0;
                else if (s2.y <= best[k]) hit = s * 2 + 1;
            }
        }
        int step = bg[k] * GSTEP + (hit >> 1);
        unsigned gidx =
            (unsigned)(seg * SEG + step * 64 + 2 * lane + (hit & 1));
        unsigned u = __float_as_uint(best[k]);
        u ^= (u >> 31) ? 0xFFFFFFFFu : 0x80000000u; // order-preserving
        unsigned long long key = ((unsigned long long)u << 32) | gidx;
#pragma unroll
        for (int off = 16; off > 0; off >>= 1) {
            unsigned long long o = __shfl_xor_sync(0xFFFFFFFFu, key, off);
            key = (o < key) ? o : key;
        }
        if (lane == 0) segbase[qbase + k] = key;
    }
}

// ---------------------------------------------------------------------------
// Kernel 2: per-query tile reduce (u64 min over 8 keys) + count histogram.
// ---------------------------------------------------------------------------
__global__ void dacd_reduce_count_kernel() {
    int i = blockIdx.x * blockDim.x + threadIdx.x;
    if (i >= NQ_TOTAL) return;
    unsigned long long best = g_segkeys[i];
#pragma unroll
    for (int s = 1; s < NSEG; s++) {
        unsigned long long k = g_segkeys[s * NQ_TOTAL + i];
        best = (k < best) ? k : best;
    }
    g_keys[i] = best;
    int base = i & ~(NPTS - 1);
    atomicAdd(&g_counts[base + (unsigned)(best & 0xFFFFFFFFu)], 1);
}

// ---------------------------------------------------------------------------
// Kernel 3: per-query loss + fused final reduction (ticket).
// term = 1 - exp(-10*dist)/(cnt+1e-6); dist = xx + score.
// ---------------------------------------------------------------------------
__global__ __launch_bounds__(TLOSS) void dacd_loss_kernel(
    const float* __restrict__ x, const float* __restrict__ gt,
    float* __restrict__ out)
{
    __shared__ double swarp[TLOSS / 32];

    const int i   = blockIdx.x * TLOSS + threadIdx.x;
    const int q   = i & (NPTS - 1);
    const int b   = (i >> 13) & 1;
    const int dir = (i >> 14) & 1;

    const float* qry = dir ? gt : x;

    unsigned long long key = g_keys[i];
    unsigned u = (unsigned)(key >> 32);
    unsigned orig = (u >> 31) ? (u ^ 0x80000000u) : ~u;
    float score = __uint_as_float(orig);

    float x0 = qry[(b * 3 + 0) * NPTS + q];
    float x1 = qry[(b * 3 + 1) * NPTS + q];
    float x2 = qry[(b * 3 + 2) * NPTS + q];
    float xx = fmaf(x0, x0, fmaf(x1, x1, x2 * x2));
    float dist = xx + score;

    int cnt = g_counts[(i & ~(NPTS - 1)) + (unsigned)(key & 0xFFFFFFFFu)];
    float w = 1.0f / ((float)cnt + 1e-6f);
    double v = (double)(1.0f - expf(-10.0f * dist) * w);

#pragma unroll
    for (int off = 16; off > 0; off >>= 1)
        v += __shfl_down_sync(0xFFFFFFFFu, v, off);

    int lane = threadIdx.x & 31, wid = threadIdx.x >> 5;
    if (lane == 0) swarp[wid] = v;
    __syncthreads();
    if (wid == 0) {
        v = (lane < TLOSS / 32) ? swarp[lane] : 0.0;
#pragma unroll
        for (int off = 4; off > 0; off >>= 1)
            v += __shfl_down_sync(0xFFFFFFFFu, v, off);
        if (lane == 0) {
            atomicAdd(&g_sum, v);
            __threadfence();
            unsigned t = atomicAdd(&g_done, 1u);
            if (t == LOSS_BLOCKS - 1)
                out[0] = (float)(g_sum / (double)(NPTS * 2 * NB));
        }
    }
}

extern "C" void kernel_launch(void* const* d_in, const int* in_sizes, int n_in,
                              void* d_out, int out_size) {
    const float* x  = (const float*)d_in[0];
    const float* gt = (const float*)d_in[1];
    float* out = (float*)d_out;

    dacd_nn_kernel<<<NN_BLOCKS, TNN>>>(x, gt);
    dacd_reduce_count_kernel<<<(NQ_TOTAL + 255) / 256, 256>>>();
    dacd_loss_kernel<<<LOSS_BLOCKS, TLOSS>>>(x, gt, out);
}

// round 14
// speedup vs baseline: 2.8871x; 2.8871x over previous
#include <cuda_runtime.h>
#include <math.h>
#include <stdint.h>

#define NPTS    8192
#define NB      2
#define TNN     128                        // threads per NN block
#define QPT     4                          // queries per thread
#define QCHUNK  (TNN * QPT)                // 512 queries per block
#define SEG     512                        // candidate segment
#define GRP     8                          // tracking-group size (2 quads)
#define NSEG    (NPTS / SEG)               // 16
#define NQCHUNK (NPTS / QCHUNK)            // 16
#define NQ_TOTAL (2 * NB * NPTS)           // 32768
#define NN_BLOCKS (2 * NB * NQCHUNK * NSEG)   // 1024
#define TLOSS   256
#define LOSS_BLOCKS (NQ_TOTAL / TLOSS)        // 128

// Scratch. g_segkeys[seg][global_q]: per-segment winner, plain stores (every
// slot rewritten each replay -> no init needed). Key packs
// (order-preserving score bits << 32 | candidate idx): u64 min == (min score,
// lowest idx), matching the reference argmin tie-break.
__device__ unsigned long long g_segkeys[NSEG * NQ_TOTAL];
__device__ unsigned long long g_keys[NQ_TOTAL];
__device__ int                g_counts[NQ_TOTAL];
__device__ double             g_sum;
__device__ unsigned int       g_done;

// ---- f32x2 packed FMA (sm_103a) -------------------------------------------
__device__ __forceinline__ unsigned long long ffma2(
    unsigned long long a, unsigned long long b, unsigned long long c) {
    unsigned long long d;
    asm("fma.rn.f32x2 %0, %1, %2, %3;" : "=l"(d) : "l"(a), "l"(b), "l"(c));
    return d;
}
__device__ __forceinline__ unsigned long long fdup2(float v) {
    unsigned long long r;
    asm("mov.b64 %0, {%1, %1};" : "=l"(r) : "f"(v));
    return r;
}
__device__ __forceinline__ float2 unpack2(unsigned long long v) {
    float2 r;
    asm("mov.b64 {%0, %1}, %2;" : "=f"(r.x), "=f"(r.y) : "l"(v));
    return r;
}

// ---------------------------------------------------------------------------
// Kernel 1: nearest-neighbor scan (R6 config: best measured NN @ 60.3us).
// score(q, m) = ||c_m||^2 - 2 <x_q, c_m>  (same argmin as full sq-dist)
// 4 queries/thread; SoA SMEM candidates; FFMA2 packed scores; fminf streams;
// (value, group-of-8) tracked; intra-group index recovered by bit-identical
// recompute over just 2 quads (was 8 -> 75% less epilogue LDS).
// Also zeroes counts / sum / ticket.
// ---------------------------------------------------------------------------
__global__ __launch_bounds__(TNN) void dacd_nn_kernel(
    const float* __restrict__ x, const float* __restrict__ gt)
{
    __shared__ __align__(16) float sc0[SEG];
    __shared__ __align__(16) float sc1[SEG];
    __shared__ __align__(16) float sc2[SEG];
    __shared__ __align__(16) float sw [SEG];

    const int blk = blockIdx.x;
    const int seg = blk & (NSEG - 1);            // bits [0,4)
    const int qc  = (blk >> 4) & (NQCHUNK - 1);  // bits [4,8)
    const int b   = (blk >> 8) & 1;
    const int dir = (blk >> 9) & 1;

    // Replace init kernel: each block zeroes its slice of counts.
    if (threadIdx.x < NQ_TOTAL / NN_BLOCKS)      // 32
        g_counts[blk * (NQ_TOTAL / NN_BLOCKS) + threadIdx.x] = 0;
    if (blk == 0 && threadIdx.x == 0) { g_sum = 0.0; g_done = 0u; }

    const float* qry = dir ? gt : x;
    const float* cnd = dir ? x : gt;

    const float* c0p = cnd + (b * 3 + 0) * NPTS + seg * SEG;
    const float* c1p = cnd + (b * 3 + 1) * NPTS + seg * SEG;
    const float* c2p = cnd + (b * 3 + 2) * NPTS + seg * SEG;

    for (int m = threadIdx.x; m < SEG; m += TNN) {
        float c0 = c0p[m], c1 = c1p[m], c2 = c2p[m];
        sc0[m] = c0; sc1[m] = c1; sc2[m] = c2;
        sw[m]  = fmaf(c0, c0, fmaf(c1, c1, c2 * c2));
    }
    __syncthreads();

    const float* qb = qry + b * 3 * NPTS;
    unsigned long long n0[QPT], n1[QPT], n2[QPT];
#pragma unroll
    for (int k = 0; k < QPT; k++) {
        int q = qc * QCHUNK + k * TNN + threadIdx.x;
        n0[k] = fdup2(-2.0f * qb[0 * NPTS + q]);
        n1[k] = fdup2(-2.0f * qb[1 * NPTS + q]);
        n2[k] = fdup2(-2.0f * qb[2 * NPTS + q]);
    }

    const float INF = __int_as_float(0x7f800000);
    float best[QPT];
    int   bg[QPT];
#pragma unroll
    for (int k = 0; k < QPT; k++) { best[k] = INF; bg[k] = 0; }

#pragma unroll 4
    for (int grp = 0; grp < SEG / GRP; grp++) {           // 64 groups
        float qm0[QPT], qm1[QPT];

#pragma unroll
        for (int sg = 0; sg < GRP / 4; sg++) {            // 2 quads
            const int m = grp * GRP + sg * 4;
            ulonglong2 C0 = *(const ulonglong2*)(sc0 + m);
            ulonglong2 C1 = *(const ulonglong2*)(sc1 + m);
            ulonglong2 C2 = *(const ulonglong2*)(sc2 + m);
            ulonglong2 W  = *(const ulonglong2*)(sw  + m);
#pragma unroll
            for (int k = 0; k < QPT; k++) {
                unsigned long long t0 = ffma2(n2[k], C2.x, W.x);
                t0 = ffma2(n1[k], C1.x, t0);
                t0 = ffma2(n0[k], C0.x, t0);
                unsigned long long t1 = ffma2(n2[k], C2.y, W.y);
                t1 = ffma2(n1[k], C1.y, t1);
                t1 = ffma2(n0[k], C0.y, t1);
                float2 p = unpack2(t0);
                float2 r = unpack2(t1);
                float qm = fminf(fminf(p.x, p.y), fminf(r.x, r.y));
                if (sg == 0) qm0[k] = qm; else qm1[k] = qm;
            }
        }
#pragma unroll
        for (int k = 0; k < QPT; k++) {
            float gm = fminf(qm0[k], qm1[k]);
            bool sel = gm < best[k];        // strict: earlier group wins ties
            bg[k]   = sel ? grp : bg[k];
            best[k] = fminf(best[k], gm);
        }
    }

    // Epilogue: rescan winning group (2 quads) bit-identically; FIRST
    // candidate (index order) achieving the min; plain coalesced store.
    unsigned long long* segbase =
        g_segkeys + seg * NQ_TOTAL + (dir * NB + b) * NPTS;
#pragma unroll 1
    for (int k = 0; k < QPT; k++) {
        int jj = -1;
        const int m0 = bg[k] * GRP;
#pragma unroll 1
        for (int sg = 0; sg < GRP / 4 && jj < 0; sg++) {  // <= 2 quads
            const int m = m0 + sg * 4;
            ulonglong2 C0 = *(const ulonglong2*)(sc0 + m);
            ulonglong2 C1 = *(const ulonglong2*)(sc1 + m);
            ulonglong2 C2 = *(const ulonglong2*)(sc2 + m);
            ulonglong2 W  = *(const ulonglong2*)(sw  + m);
            unsigned long long t0 = ffma2(n2[k], C2.x, W.x);
            t0 = ffma2(n1[k], C1.x, t0);
            t0 = ffma2(n0[k], C0.x, t0);
            unsigned long long t1 = ffma2(n2[k], C2.y, W.y);
            t1 = ffma2(n1[k], C1.y, t1);
            t1 = ffma2(n0[k], C0.y, t1);
            float2 p = unpack2(t0);
            float2 r = unpack2(t1);
            if      (p.x <= best[k]) jj = m + 0;
            else if (p.y <= best[k]) jj = m + 1;
            else if (r.x <= best[k]) jj = m + 2;
            else if (r.y <= best[k]) jj = m + 3;
        }
        unsigned u = __float_as_uint(best[k]);
        u ^= (u >> 31) ? 0xFFFFFFFFu : 0x80000000u;       // order-preserving
        int q = qc * QCHUNK + k * TNN + threadIdx.x;
        segbase[q] =
            ((unsigned long long)u << 32) | (unsigned)(seg * SEG + jj);
    }
}

// ---------------------------------------------------------------------------
// Kernel 2: per-query segment reduce (u64 min over 16 keys) + count histogram.
// ---------------------------------------------------------------------------
__global__ void dacd_reduce_count_kernel() {
    int i = blockIdx.x * blockDim.x + threadIdx.x;
    if (i >= NQ_TOTAL) return;
    unsigned long long best = g_segkeys[i];
#pragma unroll
    for (int s = 1; s < NSEG; s++) {
        unsigned long long k = g_segkeys[s * NQ_TOTAL + i];
        best = (k < best) ? k : best;
    }
    g_keys[i] = best;
    int base = i & ~(NPTS - 1);
    atomicAdd(&g_counts[base + (unsigned)(best & 0xFFFFFFFFu)], 1);
}

// ---------------------------------------------------------------------------
// Kernel 3: per-query loss + fused final reduction (ticket).
// term = 1 - exp(-10*dist)/(cnt+1e-6); dist = xx + score.
// ---------------------------------------------------------------------------
__global__ __launch_bounds__(TLOSS) void dacd_loss_kernel(
    const float* __restrict__ x, const float* __restrict__ gt,
    float* __restrict__ out)
{
    __shared__ double swarp[TLOSS / 32];

    const int i   = blockIdx.x * TLOSS + threadIdx.x;
    const int q   = i & (NPTS - 1);
    const int b   = (i >> 13) & 1;
    const int dir = (i >> 14) & 1;

    const float* qry = dir ? gt : x;

    unsigned long long key = g_keys[i];
    unsigned u = (unsigned)(key >> 32);
    unsigned orig = (u >> 31) ? (u ^ 0x80000000u) : ~u;
    float score = __uint_as_float(orig);

    float x0 = qry[(b * 3 + 0) * NPTS + q];
    float x1 = qry[(b * 3 + 1) * NPTS + q];
    float x2 = qry[(b * 3 + 2) * NPTS + q];
    float xx = fmaf(x0, x0, fmaf(x1, x1, x2 * x2));
    float dist = xx + score;

    int cnt = g_counts[(i & ~(NPTS - 1)) + (unsigned)(key & 0xFFFFFFFFu)];
    float w = 1.0f / ((float)cnt + 1e-6f);
    double v = (double)(1.0f - expf(-10.0f * dist) * w);

#pragma unroll
    for (int off = 16; off > 0; off >>= 1)
        v += __shfl_down_sync(0xFFFFFFFFu, v, off);

    int lane = threadIdx.x & 31, wid = threadIdx.x >> 5;
    if (lane == 0) swarp[wid] = v;
    __syncthreads();
    if (wid == 0) {
        v = (lane < TLOSS / 32) ? swarp[lane] : 0.0;
#pragma unroll
        for (int off = 4; off > 0; off >>= 1)
            v += __shfl_down_sync(0xFFFFFFFFu, v, off);
        if (lane == 0) {
            atomicAdd(&g_sum, v);
            __threadfence();
            unsigned t = atomicAdd(&g_done, 1u);
            if (t == LOSS_BLOCKS - 1)
                out[0] = (float)(g_sum / (double)(NPTS * 2 * NB));
        }
    }
}

extern "C" void kernel_launch(void* const* d_in, const int* in_sizes, int n_in,
                              void* d_out, int out_size) {
    const float* x  = (const float*)d_in[0];
    const float* gt = (const float*)d_in[1];
    float* out = (float*)d_out;

    dacd_nn_kernel<<<NN_BLOCKS, TNN>>>(x, gt);
    dacd_reduce_count_kernel<<<(NQ_TOTAL + 255) / 256, 256>>>();
    dacd_loss_kernel<<<LOSS_BLOCKS, TLOSS>>>(x, gt, out);
}